// round 11
// baseline (speedup 1.0000x reference)
#include <cuda_runtime.h>
#include <cstdint>

#define D_MODEL 1024
#define N_HEADS 16
#define D_HEAD  64
#define BATCH   4
#define SEQ     2048
#define M_TOT   (BATCH * SEQ)   // 8192

// Scratch (device globals: allocation-free per harness rules)
__device__ float g_Q[(size_t)BATCH * N_HEADS * SEQ * D_HEAD];   // [b,h,s,dh]
__device__ float g_K[(size_t)BATCH * N_HEADS * SEQ * D_HEAD];
__device__ float g_V[(size_t)BATCH * N_HEADS * SEQ * D_HEAD];
__device__ float g_ctx[(size_t)M_TOT * D_MODEL];                // [b*s, d]

// ---------------------------------------------------------------------------
// tf32 helpers
// ---------------------------------------------------------------------------
__device__ __forceinline__ uint32_t f2tf32(float f) {
    uint32_t u;
    asm("cvt.rna.tf32.f32 %0, %1;" : "=r"(u) : "f"(f));
    return u;
}
__device__ __forceinline__ float f2tf32f(float f) {
    return __uint_as_float(f2tf32(f));
}

__device__ __forceinline__ void mma_tf32_16x8x8(
    float c[4], const uint32_t a[4], const uint32_t b[2])
{
    asm volatile(
        "mma.sync.aligned.m16n8k8.row.col.f32.tf32.tf32.f32 "
        "{%0,%1,%2,%3}, {%4,%5,%6,%7}, {%8,%9}, {%0,%1,%2,%3};"
        : "+f"(c[0]), "+f"(c[1]), "+f"(c[2]), "+f"(c[3])
        : "r"(a[0]), "r"(a[1]), "r"(a[2]), "r"(a[3]),
          "r"(b[0]), "r"(b[1]));
}

// store-side swizzle for paired-float2 layout (row-dependent, bits disjoint)
__device__ __forceinline__ int swz_store(int r) {
    return ((r & 2) << 1) | ((r & 4) >> 1) | ((r & 8) >> 3);
}

// ---------------------------------------------------------------------------
// tf32 tensor-core GEMM core v2: C_tile(128x128) = A(128xK) * W(Kx128), K=1024.
// 256 threads = 8 warps in 2(M) x 4(N); each warp 64x32 via 4x4 m16n8k8.
// Smem holds tf32-preconverted, k-PAIRED (k, k+4 adjacent float2), XOR-swizzled
// tiles; B is staged TRANSPOSED [n][kpair]. All fragment loads are LDS.64 and
// both loads and staging stores are bank-conflict-free. Global data for the
// next k-tile is prefetched into registers before the MMA loop.
// ---------------------------------------------------------------------------
__device__ __forceinline__ void gemm_tf32_core(
    const float* __restrict__ A,   // [M, 1024] row-major
    const float* __restrict__ W,   // [1024, 1024] row-major
    float acc[4][4][4], int bm, int bn)
{
    __shared__ __align__(16) float2 As2[128 * 8];   // [row][slot'] paired
    __shared__ __align__(16) float2 Bt2[128 * 8];   // [n][slot']  paired, transposed

    const int tid  = threadIdx.x;
    const int warp = tid >> 5;
    const int lane = tid & 31;
    const int g    = lane >> 2;     // 0..7
    const int t    = lane & 3;      // 0..3
    const int m_warp = (warp & 1) * 64;
    const int n_warp = (warp >> 1) * 32;

    // ---- staging assignments ----
    const int arow = tid & 127;             // A: one row, k-half ah
    const int ah   = tid >> 7;              // 0 or 1 (k 0..7 / 8..15)
    const int aswz = swz_store(arow);
    const int q4   = tid >> 5;              // B: 0..7
    const int bkk  = (q4 & 3) + ((q4 >> 2) << 3);   // {0..3, 8..11}
    const int bslot = ((bkk >> 3) << 2) + (bkk & 3);

    // ---- precomputed fragment float2-indices (s=0; s=1 is idx^4) ----
    const int swzlo = ((g & 2) << 1) | ((g & 4) >> 1);
    int idxA0[4], idxA1[4], idxB[4];
    #pragma unroll
    for (int i = 0; i < 4; i++) {
        int rlo = m_warp + i * 16 + g;
        idxA0[i] = rlo * 8 + (t ^ swzlo);
        idxA1[i] = (rlo + 8) * 8 + (t ^ swzlo ^ 1);
    }
    #pragma unroll
    for (int j = 0; j < 4; j++) {
        int n = n_warp + j * 8 + g;
        idxB[j] = n * 8 + (t ^ swzlo ^ (j & 1));
    }

    // ---- prefetch k0 = 0 ----
    float4 pa0 = *reinterpret_cast<const float4*>(
        &A[(size_t)(bm + arow) * 1024 + ah * 8]);
    float4 pa1 = *reinterpret_cast<const float4*>(
        &A[(size_t)(bm + arow) * 1024 + ah * 8 + 4]);
    float pblo[4], pbhi[4];
    #pragma unroll
    for (int i = 0; i < 4; i++) {
        pblo[i] = W[(size_t)bkk       * 1024 + bn + lane + 32 * i];
        pbhi[i] = W[(size_t)(bkk + 4) * 1024 + bn + lane + 32 * i];
    }

    for (int k0 = 0; k0 < 1024; k0 += 16) {
        // ---- store staged tile (tf32-converted, paired, swizzled) ----
        {
            float av[8] = {pa0.x, pa0.y, pa0.z, pa0.w, pa1.x, pa1.y, pa1.z, pa1.w};
            #pragma unroll
            for (int q = 0; q < 4; q++) {
                int slot = ah * 4 + q;
                As2[arow * 8 + (slot ^ aswz)] =
                    make_float2(f2tf32f(av[q]), f2tf32f(av[q + 4]));
            }
            #pragma unroll
            for (int i = 0; i < 4; i++) {
                int n = lane + 32 * i;
                Bt2[n * 8 + (bslot ^ swz_store(n))] =
                    make_float2(f2tf32f(pblo[i]), f2tf32f(pbhi[i]));
            }
        }
        __syncthreads();

        // ---- prefetch next k-tile (overlaps with MMA below) ----
        if (k0 + 16 < 1024) {
            int kn = k0 + 16;
            pa0 = *reinterpret_cast<const float4*>(
                &A[(size_t)(bm + arow) * 1024 + kn + ah * 8]);
            pa1 = *reinterpret_cast<const float4*>(
                &A[(size_t)(bm + arow) * 1024 + kn + ah * 8 + 4]);
            #pragma unroll
            for (int i = 0; i < 4; i++) {
                pblo[i] = W[(size_t)(kn + bkk)     * 1024 + bn + lane + 32 * i];
                pbhi[i] = W[(size_t)(kn + bkk + 4) * 1024 + bn + lane + 32 * i];
            }
        }

        // ---- MMA: 2 k8 steps ----
        #pragma unroll
        for (int s = 0; s < 2; s++) {
            const int sx = s << 2;      // flip bit2 of slot' index
            uint32_t afr[4][4];
            #pragma unroll
            for (int i = 0; i < 4; i++) {
                float2 v0 = As2[idxA0[i] ^ sx];   // (k+t, k+t+4) row lo
                float2 v1 = As2[idxA1[i] ^ sx];   // row lo+8
                afr[i][0] = __float_as_uint(v0.x);
                afr[i][1] = __float_as_uint(v1.x);
                afr[i][2] = __float_as_uint(v0.y);
                afr[i][3] = __float_as_uint(v1.y);
            }
            uint32_t bfr[4][2];
            #pragma unroll
            for (int j = 0; j < 4; j++) {
                float2 v = Bt2[idxB[j] ^ sx];
                bfr[j][0] = __float_as_uint(v.x);
                bfr[j][1] = __float_as_uint(v.y);
            }
            #pragma unroll
            for (int i = 0; i < 4; i++)
                #pragma unroll
                for (int j = 0; j < 4; j++)
                    mma_tf32_16x8x8(acc[i][j], afr[i], bfr[j]);
        }
        __syncthreads();
    }
}

// ---------------------------------------------------------------------------
// QKV projection: out = x @ W_{q,k,v} + b, written in [b,h,s,dh] layout.
// ---------------------------------------------------------------------------
__global__ __launch_bounds__(256, 2)
void qkv_gemm_kernel(const float* __restrict__ x,
                     const float* __restrict__ Wq, const float* __restrict__ bq,
                     const float* __restrict__ Wk, const float* __restrict__ bk,
                     const float* __restrict__ Wv, const float* __restrict__ bv)
{
    const float* W; const float* bias; float* out;
    if      (blockIdx.z == 0) { W = Wq; bias = bq; out = g_Q; }
    else if (blockIdx.z == 1) { W = Wk; bias = bk; out = g_K; }
    else                      { W = Wv; bias = bv; out = g_V; }

    const int bm = blockIdx.x * 128;
    const int bn = blockIdx.y * 128;

    float acc[4][4][4];
    #pragma unroll
    for (int i = 0; i < 4; i++)
        #pragma unroll
        for (int j = 0; j < 4; j++)
            #pragma unroll
            for (int r = 0; r < 4; r++) acc[i][j][r] = 0.f;

    gemm_tf32_core(x, W, acc, bm, bn);

    const int warp   = threadIdx.x >> 5;
    const int lane   = threadIdx.x & 31;
    const int gID    = lane >> 2;
    const int tID    = lane & 3;
    const int m_warp = (warp & 1) * 64;
    const int n_warp = (warp >> 1) * 32;

    #pragma unroll
    for (int i = 0; i < 4; i++) {
        #pragma unroll
        for (int j = 0; j < 4; j++) {
            int n0 = bn + n_warp + j * 8 + tID * 2;
            int h  = n0 >> 6;
            int dh = n0 & 63;
            float b0v = bias[n0], b1v = bias[n0 + 1];
            #pragma unroll
            for (int rr = 0; rr < 2; rr++) {
                int m = bm + m_warp + i * 16 + gID + rr * 8;
                int b = m >> 11;
                int s = m & (SEQ - 1);
                float* dst = &out[(((size_t)(b * N_HEADS + h) * SEQ + s) * D_HEAD) + dh];
                float2 v = make_float2(acc[i][j][rr * 2] + b0v,
                                       acc[i][j][rr * 2 + 1] + b1v);
                *reinterpret_cast<float2*>(dst) = v;
            }
        }
    }
}

// ---------------------------------------------------------------------------
// Output projection: out = ctx @ W_o + b_o   (row-major [M, D])
// ---------------------------------------------------------------------------
__global__ __launch_bounds__(256, 2)
void out_gemm_kernel(const float* __restrict__ Wo,
                     const float* __restrict__ bo,
                     float* __restrict__ out)
{
    const int bm = blockIdx.x * 128;
    const int bn = blockIdx.y * 128;

    float acc[4][4][4];
    #pragma unroll
    for (int i = 0; i < 4; i++)
        #pragma unroll
        for (int j = 0; j < 4; j++)
            #pragma unroll
            for (int r = 0; r < 4; r++) acc[i][j][r] = 0.f;

    gemm_tf32_core(g_ctx, Wo, acc, bm, bn);

    const int warp   = threadIdx.x >> 5;
    const int lane   = threadIdx.x & 31;
    const int gID    = lane >> 2;
    const int tID    = lane & 3;
    const int m_warp = (warp & 1) * 64;
    const int n_warp = (warp >> 1) * 32;

    #pragma unroll
    for (int i = 0; i < 4; i++) {
        #pragma unroll
        for (int j = 0; j < 4; j++) {
            int n0 = bn + n_warp + j * 8 + tID * 2;
            float b0v = bo[n0], b1v = bo[n0 + 1];
            #pragma unroll
            for (int rr = 0; rr < 2; rr++) {
                int m = bm + m_warp + i * 16 + gID + rr * 8;
                float2 v = make_float2(acc[i][j][rr * 2] + b0v,
                                       acc[i][j][rr * 2 + 1] + b1v);
                *reinterpret_cast<float2*>(&out[(size_t)m * D_MODEL + n0]) = v;
            }
        }
    }
}

// ---------------------------------------------------------------------------
// Causal flash attention with tf32 tensor cores (unchanged from R6).
// ---------------------------------------------------------------------------
__global__ __launch_bounds__(128, 4)
void flash_attn_tc_kernel()
{
    __shared__ __align__(16) float Qs[64][68];
    __shared__ __align__(16) float Ks[32][68];
    __shared__ __align__(16) float Vs[32][72];
    __shared__ __align__(16) float Ps[64][36];

    const int tid  = threadIdx.x;
    const int warp = tid >> 5;
    const int lane = tid & 31;
    const int gID  = lane >> 2;
    const int tID  = lane & 3;
    const int qt   = blockIdx.x;
    const int bh   = blockIdx.y;
    const int qbase = qt << 6;
    const int r0   = warp << 4;

    const float sc = 0.125f * 1.44269504088896340736f;

    {
        const float* qsrc = &g_Q[((size_t)bh * SEQ + qbase) * D_HEAD];
        int row  = tid >> 1;
        int colb = (tid & 1) * 32;
        #pragma unroll
        for (int i = 0; i < 8; i++) {
            float4 v = *reinterpret_cast<const float4*>(
                &qsrc[(size_t)row * 64 + colb + i * 4]);
            Qs[row][colb + i*4 + 0] = f2tf32f(v.x * sc);
            Qs[row][colb + i*4 + 1] = f2tf32f(v.y * sc);
            Qs[row][colb + i*4 + 2] = f2tf32f(v.z * sc);
            Qs[row][colb + i*4 + 3] = f2tf32f(v.w * sc);
        }
    }

    float m0 = -1e30f, m1 = -1e30f, l0 = 0.f, l1 = 0.f;
    float co[8][4];
    #pragma unroll
    for (int j = 0; j < 8; j++)
        #pragma unroll
        for (int r = 0; r < 4; r++) co[j][r] = 0.f;

    const float* Kb = &g_K[(size_t)bh * SEQ * D_HEAD];
    const float* Vb = &g_V[(size_t)bh * SEQ * D_HEAD];

    __syncthreads();

    const int ntiles = 2 * qt + 2;
    for (int t = 0; t < ntiles; t++) {
        {
            int row  = tid >> 2;
            int colb = (tid & 3) * 16;
            const float* ks = Kb + ((size_t)t * 32 + row) * 64 + colb;
            const float* vs = Vb + ((size_t)t * 32 + row) * 64 + colb;
            #pragma unroll
            for (int i = 0; i < 4; i++) {
                float4 kv = *reinterpret_cast<const float4*>(&ks[i * 4]);
                Ks[row][colb + i*4 + 0] = f2tf32f(kv.x);
                Ks[row][colb + i*4 + 1] = f2tf32f(kv.y);
                Ks[row][colb + i*4 + 2] = f2tf32f(kv.z);
                Ks[row][colb + i*4 + 3] = f2tf32f(kv.w);
                float4 vv = *reinterpret_cast<const float4*>(&vs[i * 4]);
                Vs[row][colb + i*4 + 0] = f2tf32f(vv.x);
                Vs[row][colb + i*4 + 1] = f2tf32f(vv.y);
                Vs[row][colb + i*4 + 2] = f2tf32f(vv.z);
                Vs[row][colb + i*4 + 3] = f2tf32f(vv.w);
            }
        }
        __syncthreads();

        float sfrag[4][4];
        #pragma unroll
        for (int j = 0; j < 4; j++)
            #pragma unroll
            for (int r = 0; r < 4; r++) sfrag[j][r] = 0.f;

        #pragma unroll
        for (int k8 = 0; k8 < 64; k8 += 8) {
            uint32_t a[4];
            a[0] = __float_as_uint(Qs[r0 + gID    ][k8 + tID    ]);
            a[1] = __float_as_uint(Qs[r0 + gID + 8][k8 + tID    ]);
            a[2] = __float_as_uint(Qs[r0 + gID    ][k8 + tID + 4]);
            a[3] = __float_as_uint(Qs[r0 + gID + 8][k8 + tID + 4]);
            #pragma unroll
            for (int j = 0; j < 4; j++) {
                uint32_t b[2];
                b[0] = __float_as_uint(Ks[j*8 + gID][k8 + tID    ]);
                b[1] = __float_as_uint(Ks[j*8 + gID][k8 + tID + 4]);
                mma_tf32_16x8x8(sfrag[j], a, b);
            }
        }

        const int rg0 = qbase + r0 + gID;
        const int rg1 = rg0 + 8;
        if (t >= 2 * qt) {
            #pragma unroll
            for (int j = 0; j < 4; j++) {
                int key = t * 32 + j * 8 + tID * 2;
                if (key     > rg0) sfrag[j][0] = -1e30f;
                if (key + 1 > rg0) sfrag[j][1] = -1e30f;
                if (key     > rg1) sfrag[j][2] = -1e30f;
                if (key + 1 > rg1) sfrag[j][3] = -1e30f;
            }
        }

        float tm0 = -1e30f, tm1 = -1e30f;
        #pragma unroll
        for (int j = 0; j < 4; j++) {
            tm0 = fmaxf(tm0, fmaxf(sfrag[j][0], sfrag[j][1]));
            tm1 = fmaxf(tm1, fmaxf(sfrag[j][2], sfrag[j][3]));
        }
        tm0 = fmaxf(tm0, __shfl_xor_sync(0xffffffffu, tm0, 1));
        tm0 = fmaxf(tm0, __shfl_xor_sync(0xffffffffu, tm0, 2));
        tm1 = fmaxf(tm1, __shfl_xor_sync(0xffffffffu, tm1, 1));
        tm1 = fmaxf(tm1, __shfl_xor_sync(0xffffffffu, tm1, 2));

        float mn0 = fmaxf(m0, tm0), mn1 = fmaxf(m1, tm1);
        float al0 = exp2f(m0 - mn0), al1 = exp2f(m1 - mn1);
        m0 = mn0; m1 = mn1;

        float ls0 = 0.f, ls1 = 0.f;
        #pragma unroll
        for (int j = 0; j < 4; j++) {
            float p0 = f2tf32f(exp2f(sfrag[j][0] - m0));
            float p1 = f2tf32f(exp2f(sfrag[j][1] - m0));
            float p2 = f2tf32f(exp2f(sfrag[j][2] - m1));
            float p3 = f2tf32f(exp2f(sfrag[j][3] - m1));
            ls0 += p0 + p1;
            ls1 += p2 + p3;
            int col = j * 8 + tID * 2;
            *reinterpret_cast<float2*>(&Ps[r0 + gID    ][col]) = make_float2(p0, p1);
            *reinterpret_cast<float2*>(&Ps[r0 + gID + 8][col]) = make_float2(p2, p3);
        }
        ls0 += __shfl_xor_sync(0xffffffffu, ls0, 1);
        ls0 += __shfl_xor_sync(0xffffffffu, ls0, 2);
        ls1 += __shfl_xor_sync(0xffffffffu, ls1, 1);
        ls1 += __shfl_xor_sync(0xffffffffu, ls1, 2);
        l0 = l0 * al0 + ls0;
        l1 = l1 * al1 + ls1;

        #pragma unroll
        for (int j = 0; j < 8; j++) {
            co[j][0] *= al0; co[j][1] *= al0;
            co[j][2] *= al1; co[j][3] *= al1;
        }

        __syncwarp();

        #pragma unroll
        for (int k8 = 0; k8 < 32; k8 += 8) {
            uint32_t a[4];
            a[0] = __float_as_uint(Ps[r0 + gID    ][k8 + tID    ]);
            a[1] = __float_as_uint(Ps[r0 + gID + 8][k8 + tID    ]);
            a[2] = __float_as_uint(Ps[r0 + gID    ][k8 + tID + 4]);
            a[3] = __float_as_uint(Ps[r0 + gID + 8][k8 + tID + 4]);
            #pragma unroll
            for (int jn = 0; jn < 8; jn++) {
                uint32_t b[2];
                b[0] = __float_as_uint(Vs[k8 + tID    ][jn*8 + gID]);
                b[1] = __float_as_uint(Vs[k8 + tID + 4][jn*8 + gID]);
                mma_tf32_16x8x8(co[jn], a, b);
            }
        }
        __syncthreads();
    }

    const float inv0 = 1.f / l0;
    const float inv1 = 1.f / l1;
    const int b = bh >> 4;
    const int h = bh & 15;
    const int grow0 = qbase + r0 + gID;
    const int grow1 = grow0 + 8;
    #pragma unroll
    for (int jn = 0; jn < 8; jn++) {
        int col = h * 64 + jn * 8 + tID * 2;
        *reinterpret_cast<float2*>(&g_ctx[(size_t)(b * SEQ + grow0) * D_MODEL + col]) =
            make_float2(co[jn][0] * inv0, co[jn][1] * inv0);
        *reinterpret_cast<float2*>(&g_ctx[(size_t)(b * SEQ + grow1) * D_MODEL + col]) =
            make_float2(co[jn][2] * inv1, co[jn][3] * inv1);
    }
}

// ---------------------------------------------------------------------------
extern "C" void kernel_launch(void* const* d_in, const int* in_sizes, int n_in,
                              void* d_out, int out_size)
{
    const float* x   = (const float*)d_in[0];
    const float* W_q = (const float*)d_in[1];
    const float* b_q = (const float*)d_in[2];
    const float* W_k = (const float*)d_in[3];
    const float* b_k = (const float*)d_in[4];
    const float* W_v = (const float*)d_in[5];
    const float* b_v = (const float*)d_in[6];
    const float* W_o = (const float*)d_in[7];
    const float* b_o = (const float*)d_in[8];
    float* out = (float*)d_out;

    dim3 gProj(M_TOT / 128, D_MODEL / 128, 3);
    qkv_gemm_kernel<<<gProj, 256>>>(x, W_q, b_q, W_k, b_k, W_v, b_v);

    dim3 gAttn(SEQ / 64, BATCH * N_HEADS);
    flash_attn_tc_kernel<<<gAttn, 128>>>();

    dim3 gOut(M_TOT / 128, D_MODEL / 128);
    out_gemm_kernel<<<gOut, 256>>>(W_o, b_o, out);
}